// round 1
// baseline (speedup 1.0000x reference)
#include <cuda_runtime.h>
#include <math.h>

// Problem constants (fixed by the reference setup)
#define BB   2
#define KK   8
#define CC   256
#define HH   128
#define WW2  128
#define HW   (HH * WW2)      // 16384
#define SS   2048            // NUM_SAMPLES
#define SIM_TH 0.95f
#define EPS_DEN 1e-6f
#define EPS_NRM 1e-12f

// Tiling for the Gram kernel
#define TM 128               // tile rows (s)
#define TN 128               // tile cols (t)
#define BK 16                // k-chunk (channels)
#define NT 16                // number of tiles per dim: SS / TM
#define NPAIR ((NT * (NT + 1)) / 2)   // 136 upper-tri tile pairs per batch

// Scratch in device globals (no allocation allowed)
__device__ float g_f[BB][SS][CC];      // normalized sampled features, c contiguous
__device__ float g_m[BB][KK][SS];      // sigmoid(mask logits) at samples
__device__ float g_num;
__device__ float g_den;

// ---------------------------------------------------------------------------
// Kernel 1: gather + normalize features (one warp per sample),
//           gather + sigmoid masks (first 64 threads of each block),
//           zero the accumulators (global thread 0).
// grid: 512 blocks x 256 threads  (512*8 warps = 4096 samples = B*S)
// ---------------------------------------------------------------------------
__global__ void gather_kernel(const float* __restrict__ masks,
                              const float* __restrict__ feats,
                              const int*   __restrict__ indices)
{
    const int tid = threadIdx.x;
    const int gtid = blockIdx.x * blockDim.x + tid;

    if (gtid == 0) { g_num = 0.0f; g_den = 0.0f; }

    // --- mask gather: 32768 entries, 64 per block ---
    if (tid < 64) {
        int e = blockIdx.x * 64 + tid;           // 512*64 = 32768 = B*K*S
        int b = e / (KK * SS);
        int r = e % (KK * SS);
        int k = r / SS;
        int s = r % SS;
        int hw = indices[b * SS + s];
        float x = masks[(b * KK + k) * HW + hw];
        g_m[b][k][s] = 1.0f / (1.0f + expf(-x));
    }

    // --- feature gather + L2 normalize: one warp per sample ---
    const int warp = gtid >> 5;                  // global warp id, 0..4095
    const int lane = tid & 31;
    const int b = warp / SS;
    const int s = warp % SS;
    const int hw = indices[b * SS + s];

    float v[8];
    float ss = 0.0f;
#pragma unroll
    for (int u = 0; u < 8; u++) {
        int c = u * 32 + lane;
        float x = feats[((size_t)(b * CC + c)) * HW + hw];
        v[u] = x;
        ss += x * x;
    }
#pragma unroll
    for (int off = 16; off > 0; off >>= 1)
        ss += __shfl_xor_sync(0xFFFFFFFFu, ss, off);

    float inv = 1.0f / fmaxf(sqrtf(ss), EPS_NRM);
#pragma unroll
    for (int u = 0; u < 8; u++) {
        int c = u * 32 + lane;
        g_f[b][s][c] = v[u] * inv;
    }
}

// ---------------------------------------------------------------------------
// Kernel 2: symmetric tiled Gram + fused affinity accumulation.
// One block per (batch, upper-tri tile pair). 256 threads, 128x128 tile,
// 8x8 per thread with strided (CUTLASS-style) fragments: conflict-free smem.
// ---------------------------------------------------------------------------
__global__ __launch_bounds__(256)
void gram_affinity_kernel()
{
    __shared__ float As[BK][TM];
    __shared__ float Bs[BK][TN];
    __shared__ float Ms[KK][TM];
    __shared__ float Mt[KK][TN];
    __shared__ float red[16];

    const int tid = threadIdx.x;
    const int b = blockIdx.x / NPAIR;
    int p = blockIdx.x % NPAIR;

    // decode upper-tri pair p -> (i <= j)
    int j = 0;
    while (((j + 1) * (j + 2)) / 2 <= p) j++;
    int i = p - (j * (j + 1)) / 2;

    const int s0 = i * TM;
    const int t0 = j * TN;
    const float w = (i == j) ? 1.0f : 2.0f;

    const int tx = tid & 15;     // n dim
    const int ty = tid >> 4;     // m dim

    float acc[8][8];
#pragma unroll
    for (int a = 0; a < 8; a++)
#pragma unroll
        for (int c = 0; c < 8; c++) acc[a][c] = 0.0f;

    const int lrow = tid & 127;      // load row
    const int lc4  = tid >> 7;       // 0 or 1 (then +2 on 2nd pass)

    for (int kc = 0; kc < CC; kc += BK) {
#pragma unroll
        for (int pass = 0; pass < 2; pass++) {
            int cc = lc4 + pass * 2;                  // float4 chunk 0..3
            const float4 va = *(const float4*)&g_f[b][s0 + lrow][kc + cc * 4];
            As[cc * 4 + 0][lrow] = va.x;
            As[cc * 4 + 1][lrow] = va.y;
            As[cc * 4 + 2][lrow] = va.z;
            As[cc * 4 + 3][lrow] = va.w;
            const float4 vb = *(const float4*)&g_f[b][t0 + lrow][kc + cc * 4];
            Bs[cc * 4 + 0][lrow] = vb.x;
            Bs[cc * 4 + 1][lrow] = vb.y;
            Bs[cc * 4 + 2][lrow] = vb.z;
            Bs[cc * 4 + 3][lrow] = vb.w;
        }
        __syncthreads();

#pragma unroll
        for (int k = 0; k < BK; k++) {
            float af[8], bf[8];
            const float4 a0 = *(const float4*)&As[k][ty * 4];
            const float4 a1 = *(const float4*)&As[k][64 + ty * 4];
            af[0]=a0.x; af[1]=a0.y; af[2]=a0.z; af[3]=a0.w;
            af[4]=a1.x; af[5]=a1.y; af[6]=a1.z; af[7]=a1.w;
            const float4 b0 = *(const float4*)&Bs[k][tx * 4];
            const float4 b1 = *(const float4*)&Bs[k][64 + tx * 4];
            bf[0]=b0.x; bf[1]=b0.y; bf[2]=b0.z; bf[3]=b0.w;
            bf[4]=b1.x; bf[5]=b1.y; bf[6]=b1.z; bf[7]=b1.w;
#pragma unroll
            for (int a = 0; a < 8; a++)
#pragma unroll
                for (int c = 0; c < 8; c++)
                    acc[a][c] += af[a] * bf[c];
        }
        __syncthreads();
    }

    // load m tiles: 8 x 128 each side
#pragma unroll
    for (int it = 0; it < 4; it++) {
        int q = tid + it * 256;       // 0..1023
        int k = q >> 7;               // 0..7
        int r = q & 127;
        Ms[k][r] = g_m[b][k][s0 + r];
        Mt[k][r] = g_m[b][k][t0 + r];
    }
    __syncthreads();

    // fused affinity: only pairs with sim > threshold (rare) do the k-loop
    float numL = 0.0f, denL = 0.0f;
    int rm[8], rn[8];
#pragma unroll
    for (int a = 0; a < 4; a++) { rm[a] = ty * 4 + a; rm[a + 4] = 64 + ty * 4 + a; }
#pragma unroll
    for (int c = 0; c < 4; c++) { rn[c] = tx * 4 + c; rn[c + 4] = 64 + tx * 4 + c; }

#pragma unroll
    for (int a = 0; a < 8; a++) {
#pragma unroll
        for (int c = 0; c < 8; c++) {
            if (acc[a][c] > SIM_TH) {
                denL += 1.0f;
                float d = 0.0f;
#pragma unroll
                for (int k = 0; k < KK; k++)
                    d += fabsf(Ms[k][rm[a]] - Mt[k][rn[c]]);
                numL += d;
            }
        }
    }
    numL *= w;
    denL *= w;

    // block reduction
#pragma unroll
    for (int off = 16; off > 0; off >>= 1) {
        numL += __shfl_xor_sync(0xFFFFFFFFu, numL, off);
        denL += __shfl_xor_sync(0xFFFFFFFFu, denL, off);
    }
    const int warp = tid >> 5;
    const int lane = tid & 31;
    if (lane == 0) { red[warp] = numL; red[8 + warp] = denL; }
    __syncthreads();
    if (tid == 0) {
        float n = 0.0f, d = 0.0f;
#pragma unroll
        for (int wgi = 0; wgi < 8; wgi++) { n += red[wgi]; d += red[8 + wgi]; }
        atomicAdd(&g_num, n);
        atomicAdd(&g_den, d);
    }
}

// ---------------------------------------------------------------------------
// Kernel 3: final scalar
// ---------------------------------------------------------------------------
__global__ void finalize_kernel(float* out)
{
    out[0] = g_num / (g_den + EPS_DEN);
}

extern "C" void kernel_launch(void* const* d_in, const int* in_sizes, int n_in,
                              void* d_out, int out_size)
{
    const float* masks   = (const float*)d_in[0];
    const float* feats   = (const float*)d_in[1];
    const int*   indices = (const int*)d_in[2];
    float* out = (float*)d_out;

    gather_kernel<<<512, 256>>>(masks, feats, indices);
    gram_affinity_kernel<<<BB * NPAIR, 256>>>();
    finalize_kernel<<<1, 1>>>(out);
}

// round 2
// speedup vs baseline: 3.2575x; 3.2575x over previous
#include <cuda_runtime.h>
#include <cuda_bf16.h>
#include <math.h>

// Problem constants (fixed by the reference setup)
#define BB   2
#define KK   8
#define CC   256
#define HW   16384           // 128*128
#define SS   2048            // NUM_SAMPLES
#define SIM_TH 0.95f
#define EPS_DEN 1e-6f
#define EPS_NRM 1e-12f

// Gram tiling
#define TM 128
#define TN 128
#define KC 64                // k-chunk (bf16 channels per smem stage)
#define NT (SS / TM)         // 16
#define NPAIR ((NT * (NT + 1)) / 2)   // 136

// Scratch (no allocation allowed)
__device__ __align__(16) __nv_bfloat16 g_fh[BB][SS][CC]; // normalized features, bf16
__device__ float g_m[BB][KK][SS];                         // sigmoid(masks) at samples
__device__ float g_num;
__device__ float g_den;

// ---------------------------------------------------------------------------
// Kernel 1: gather + normalize features (one warp per sample, bf16 out),
//           gather + sigmoid masks, zero accumulators.
// grid: 512 x 256
// ---------------------------------------------------------------------------
__global__ void gather_kernel(const float* __restrict__ masks,
                              const float* __restrict__ feats,
                              const int*   __restrict__ indices)
{
    const int tid = threadIdx.x;
    const int gtid = blockIdx.x * blockDim.x + tid;

    if (gtid == 0) { g_num = 0.0f; g_den = 0.0f; }

    if (tid < 64) {
        int e = blockIdx.x * 64 + tid;           // 32768 = B*K*S
        int b = e / (KK * SS);
        int r = e % (KK * SS);
        int k = r / SS;
        int s = r % SS;
        int hw = indices[b * SS + s];
        float x = masks[(b * KK + k) * HW + hw];
        g_m[b][k][s] = 1.0f / (1.0f + expf(-x));
    }

    const int warp = gtid >> 5;                  // 0..4095
    const int lane = tid & 31;
    const int b = warp / SS;
    const int s = warp % SS;
    const int hw = indices[b * SS + s];

    float v[8];
    float ss = 0.0f;
#pragma unroll
    for (int u = 0; u < 8; u++) {
        int c = u * 32 + lane;
        float x = feats[((size_t)(b * CC + c)) * HW + hw];
        v[u] = x;
        ss += x * x;
    }
#pragma unroll
    for (int off = 16; off > 0; off >>= 1)
        ss += __shfl_xor_sync(0xFFFFFFFFu, ss, off);

    float inv = 1.0f / fmaxf(sqrtf(ss), EPS_NRM);
#pragma unroll
    for (int u = 0; u < 8; u++) {
        int c = u * 32 + lane;
        g_fh[b][s][c] = __float2bfloat16(v[u] * inv);
    }
}

// ---------------------------------------------------------------------------
// Kernel 2: bf16 tensor-core Gram (mma.sync m16n8k16) + fused affinity.
// One block per (batch, upper-tri tile pair). 256 threads = 8 warps, 2x4
// warp grid, warp tile 64x32, 128x128 block tile, K chunks of 64.
// ---------------------------------------------------------------------------
#define SROW (KC + 8)   // padded smem row (bf16 elems): conflict-free ldmatrix

__global__ __launch_bounds__(256)
void gram_affinity_kernel()
{
    __shared__ __nv_bfloat16 As[TM][SROW];
    __shared__ __nv_bfloat16 Bs[TN][SROW];
    __shared__ float Ms[KK][TM];
    __shared__ float Mt[KK][TN];
    __shared__ float red[16];

    const int tid = threadIdx.x;
    const int b = blockIdx.x / NPAIR;
    int p = blockIdx.x % NPAIR;

    int j = 0;
    while (((j + 1) * (j + 2)) / 2 <= p) j++;
    int i = p - (j * (j + 1)) / 2;

    const int s0 = i * TM;
    const int t0 = j * TN;
    const float w = (i == j) ? 1.0f : 2.0f;

    const int lane = tid & 31;
    const int wid  = tid >> 5;
    const int wm   = wid & 1;       // 0..1 (64 rows each)
    const int wn   = wid >> 1;      // 0..3 (32 cols each)

    // load m tiles early (separate smem; first __syncthreads orders them)
#pragma unroll
    for (int it = 0; it < 4; it++) {
        int q = tid + it * 256;
        int k = q >> 7;
        int r = q & 127;
        Ms[k][r] = g_m[b][k][s0 + r];
        Mt[k][r] = g_m[b][k][t0 + r];
    }

    float acc[4][4][4];
#pragma unroll
    for (int im = 0; im < 4; im++)
#pragma unroll
        for (int in = 0; in < 4; in++)
#pragma unroll
            for (int r = 0; r < 4; r++) acc[im][in][r] = 0.0f;

    // precompute ldmatrix smem addresses (depend only on lane)
    // A x4: lane l -> row (l&15), col-sel (l>>4)*8 ; four m16 tiles per warp
    const int a_r   = lane & 15;
    const int a_sel = (lane >> 4) << 3;
    // B x4: lane l -> row (l&7) + ((l>>4)<<3), col-sel ((l>>3)&1)*8 ; 16 n-rows
    const int b_r   = (lane & 7) + ((lane >> 4) << 3);
    const int b_sel = ((lane >> 3) & 1) << 3;

    for (int kc = 0; kc < CC; kc += KC) {
        // stage tiles: 128 rows x 64 bf16 = 8 int4/row, 1024 int4 per tile
#pragma unroll
        for (int it = 0; it < 4; it++) {
            int idx = tid + it * 256;
            int row = idx >> 3;
            int ch  = (idx & 7) << 3;
            *(int4*)&As[row][ch] = *(const int4*)&g_fh[b][s0 + row][kc + ch];
            *(int4*)&Bs[row][ch] = *(const int4*)&g_fh[b][t0 + row][kc + ch];
        }
        __syncthreads();

#pragma unroll
        for (int kk = 0; kk < KC; kk += 16) {
            unsigned af[4][4];
#pragma unroll
            for (int im = 0; im < 4; im++) {
                unsigned addr = (unsigned)__cvta_generic_to_shared(
                    &As[wm * 64 + im * 16 + a_r][kk + a_sel]);
                asm volatile(
                    "ldmatrix.sync.aligned.m8n8.x4.shared.b16 {%0,%1,%2,%3}, [%4];"
                    : "=r"(af[im][0]), "=r"(af[im][1]), "=r"(af[im][2]), "=r"(af[im][3])
                    : "r"(addr));
            }
            unsigned bq[2][4];
#pragma unroll
            for (int q = 0; q < 2; q++) {
                unsigned addr = (unsigned)__cvta_generic_to_shared(
                    &Bs[wn * 32 + q * 16 + b_r][kk + b_sel]);
                asm volatile(
                    "ldmatrix.sync.aligned.m8n8.x4.shared.b16 {%0,%1,%2,%3}, [%4];"
                    : "=r"(bq[q][0]), "=r"(bq[q][1]), "=r"(bq[q][2]), "=r"(bq[q][3])
                    : "r"(addr));
            }
#pragma unroll
            for (int im = 0; im < 4; im++) {
#pragma unroll
                for (int in = 0; in < 4; in++) {
                    unsigned b0 = bq[in >> 1][(in & 1) * 2];
                    unsigned b1 = bq[in >> 1][(in & 1) * 2 + 1];
                    asm volatile(
                        "mma.sync.aligned.m16n8k16.row.col.f32.bf16.bf16.f32 "
                        "{%0,%1,%2,%3}, {%4,%5,%6,%7}, {%8,%9}, {%0,%1,%2,%3};"
                        : "+f"(acc[im][in][0]), "+f"(acc[im][in][1]),
                          "+f"(acc[im][in][2]), "+f"(acc[im][in][3])
                        : "r"(af[im][0]), "r"(af[im][1]), "r"(af[im][2]), "r"(af[im][3]),
                          "r"(b0), "r"(b1));
                }
            }
        }
        __syncthreads();
    }

    // fused affinity epilogue: threshold branch almost never taken
    const int gr = lane >> 2;            // group row 0..7
    const int gc = (lane & 3) * 2;       // col base
    float numL = 0.0f, denL = 0.0f;
#pragma unroll
    for (int im = 0; im < 4; im++) {
#pragma unroll
        for (int in = 0; in < 4; in++) {
#pragma unroll
            for (int r = 0; r < 4; r++) {
                if (acc[im][in][r] > SIM_TH) {
                    int row = wm * 64 + im * 16 + gr + ((r >> 1) << 3);
                    int col = wn * 32 + in * 8 + gc + (r & 1);
                    denL += 1.0f;
                    float d = 0.0f;
#pragma unroll
                    for (int k = 0; k < KK; k++)
                        d += fabsf(Ms[k][row] - Mt[k][col]);
                    numL += d;
                }
            }
        }
    }
    numL *= w;
    denL *= w;

#pragma unroll
    for (int off = 16; off > 0; off >>= 1) {
        numL += __shfl_xor_sync(0xFFFFFFFFu, numL, off);
        denL += __shfl_xor_sync(0xFFFFFFFFu, denL, off);
    }
    if (lane == 0) { red[wid] = numL; red[8 + wid] = denL; }
    __syncthreads();
    if (tid == 0) {
        float n = 0.0f, d = 0.0f;
#pragma unroll
        for (int q = 0; q < 8; q++) { n += red[q]; d += red[8 + q]; }
        atomicAdd(&g_num, n);
        atomicAdd(&g_den, d);
    }
}

// ---------------------------------------------------------------------------
__global__ void finalize_kernel(float* out)
{
    out[0] = g_num / (g_den + EPS_DEN);
}

extern "C" void kernel_launch(void* const* d_in, const int* in_sizes, int n_in,
                              void* d_out, int out_size)
{
    const float* masks   = (const float*)d_in[0];
    const float* feats   = (const float*)d_in[1];
    const int*   indices = (const int*)d_in[2];
    float* out = (float*)d_out;

    gather_kernel<<<512, 256>>>(masks, feats, indices);
    gram_affinity_kernel<<<BB * NPAIR, 256>>>();
    finalize_kernel<<<1, 1>>>(out);
}